// round 1
// baseline (speedup 1.0000x reference)
#include <cuda_runtime.h>

// ROI-align 7x7, img (B=8, 64, 64, C=1024) f32 NHWC, rois (R=32, 4) int32 [x,y,w,h].
// Output memory layout (R, B, 7, 7, C) — matches reference's transpose+reshape view.

#define POOL 7
#define IMG_H 64
#define IMG_W 64
#define CCH 1024          // channels
#define C4 (CCH / 4)      // float4 per pixel = 256

__global__ void roi_align_kernel(const float* __restrict__ img,
                                 const int*  __restrict__ rois,
                                 float* __restrict__ out,
                                 int B) {
    const int r  = blockIdx.x / (POOL * POOL);
    const int pp = blockIdx.x % (POOL * POOL);
    const int py = pp / POOL;
    const int px = pp % POOL;
    const int b  = blockIdx.y;

    const int4 roi = reinterpret_cast<const int4*>(rois)[r];  // x, y, w, h

    // Edge computation (replicates reference _edge):
    // coord = (p + 0.5) * (size / POOL) - 0.5
    // lo = max(floor(coord), 0); hi = clip(ceil(coord), 0, size-1); w = coord - floor(coord)
    const float cx = (px + 0.5f) * ((float)roi.z / (float)POOL) - 0.5f;
    const float cy = (py + 0.5f) * ((float)roi.w / (float)POOL) - 0.5f;
    const float fx = floorf(cx);
    const float fy = floorf(cy);
    const int x0 = roi.x + max(__float2int_rd(cx), 0);
    const int x1 = roi.x + min(max(__float2int_ru(cx), 0), roi.z - 1);
    const int y0 = roi.y + max(__float2int_rd(cy), 0);
    const int y1 = roi.y + min(max(__float2int_ru(cy), 0), roi.w - 1);
    const float wx = cx - fx;
    const float wy = cy - fy;

    const size_t base = (size_t)b * (IMG_H * IMG_W);
    const float4* __restrict__ p00 = reinterpret_cast<const float4*>(img) + (base + (size_t)y0 * IMG_W + x0) * C4;
    const float4* __restrict__ p01 = reinterpret_cast<const float4*>(img) + (base + (size_t)y0 * IMG_W + x1) * C4;
    const float4* __restrict__ p10 = reinterpret_cast<const float4*>(img) + (base + (size_t)y1 * IMG_W + x0) * C4;
    const float4* __restrict__ p11 = reinterpret_cast<const float4*>(img) + (base + (size_t)y1 * IMG_W + x1) * C4;

    const int c = threadIdx.x;  // 0..255, one float4 each

    const float4 v00 = p00[c];
    const float4 v01 = p01[c];
    const float4 v10 = p10[c];
    const float4 v11 = p11[c];

    float4 res;
    {
        float t, bo;
        t  = v00.x + (v01.x - v00.x) * wx;
        bo = v10.x + (v11.x - v10.x) * wx;
        res.x = t + (bo - t) * wy;
        t  = v00.y + (v01.y - v00.y) * wx;
        bo = v10.y + (v11.y - v10.y) * wx;
        res.y = t + (bo - t) * wy;
        t  = v00.z + (v01.z - v00.z) * wx;
        bo = v10.z + (v11.z - v10.z) * wx;
        res.z = t + (bo - t) * wy;
        t  = v00.w + (v01.w - v00.w) * wx;
        bo = v10.w + (v11.w - v10.w) * wx;
        res.w = t + (bo - t) * wy;
    }

    // out layout: (R, B, 7, 7, C)
    float4* __restrict__ o = reinterpret_cast<float4*>(out);
    o[(((size_t)r * B + b) * (POOL * POOL) + pp) * C4 + c] = res;
}

extern "C" void kernel_launch(void* const* d_in, const int* in_sizes, int n_in,
                              void* d_out, int out_size) {
    const float* img  = (const float*)d_in[0];
    const int*   rois = (const int*)d_in[1];
    float*       out  = (float*)d_out;

    const int R = in_sizes[1] / 4;                       // 32
    const int B = in_sizes[0] / (IMG_H * IMG_W * CCH);   // 8

    dim3 grid(R * POOL * POOL, B);
    roi_align_kernel<<<grid, C4>>>(img, rois, out, B);
}